// round 10
// baseline (speedup 1.0000x reference)
#include <cuda_runtime.h>
#include <cuda_fp16.h>
#include <cstdint>

// GRU cell B=8192, I=H=1024 fp32. mma.sync fp16 m16n8k16 (fp32 accum).
// R10: B fragments read directly from global (L2-hot, L1-cached across the
// 4 same-phase warps) — no STS/LDS for B. Only A is cp.async-staged in smem.
// Perm kernels merged. Grid raster swapped (x = n-tiles) for L2 A-locality.

#define BB 8192
#define HH 1024
#define KK 1024

// Fragment layouts (validated R4):
//  A: g_ap[((rb*64+kb)*32+lane)] = uint4{a0,a1,a2,a3}, lane=g*4+tq
//  B: g_Wh[w][((nb*64+kb)*32+lane)] = uint2{b0,b1}
__device__ __align__(16) uint4 g_xp[BB * KK / 8];
__device__ __align__(16) uint4 g_hp[BB * KK / 8];
__device__ __align__(16) uint4 g_rhp[BB * KK / 8];
__device__ __align__(16) float g_Z[BB * HH];
__device__ __align__(16) uint2 g_Wh[6][HH * KK / 4];  // 0:Wwz 1:Wuz 2:Wwr 3:Wur 4:Wu 5:Ww

__device__ __forceinline__ void cp_async16(void* sdst, const void* gsrc) {
    uint32_t s = (uint32_t)__cvta_generic_to_shared(sdst);
    asm volatile("cp.async.cg.shared.global [%0], [%1], 16;\n" :: "r"(s), "l"(gsrc));
}
__device__ __forceinline__ void cp_commit() { asm volatile("cp.async.commit_group;\n"); }
__device__ __forceinline__ void cp_wait_all() { asm volatile("cp.async.wait_group 0;\n"); }

__device__ __forceinline__ void mma16(float c[4], const uint4& a, const uint2& b) {
    asm volatile(
        "mma.sync.aligned.m16n8k16.row.col.f32.f16.f16.f32 "
        "{%0,%1,%2,%3},{%4,%5,%6,%7},{%8,%9},{%0,%1,%2,%3};\n"
        : "+f"(c[0]), "+f"(c[1]), "+f"(c[2]), "+f"(c[3])
        : "r"(a.x), "r"(a.y), "r"(a.z), "r"(a.w), "r"(b.x), "r"(b.y));
}
__device__ __forceinline__ float sig_(float v) { return 1.0f / (1.0f + __expf(-v)); }
__device__ __forceinline__ float ftanh_(float v) {
    return 1.0f - 2.0f / (1.0f + __expf(2.0f * v));
}
__device__ __forceinline__ uint32_t h2u(float a, float b) {
    __half2 h = __floats2half2_rn(a, b);
    return *reinterpret_cast<uint32_t*>(&h);
}

// ---------------------------------------------------------------------------
// Preprocess: merged A+B permute (one launch). y<2: x/h; y in [2,8): weights.
// ---------------------------------------------------------------------------
__global__ void __launch_bounds__(256) perm_all(
    const float* __restrict__ x, const float* __restrict__ hm,
    const float* __restrict__ w0, const float* __restrict__ w1,
    const float* __restrict__ w2, const float* __restrict__ w3,
    const float* __restrict__ w4, const float* __restrict__ w5) {
    if (blockIdx.y < 2) {
        const float* src = blockIdx.y ? hm : x;
        uint4* dst = blockIdx.y ? g_hp : g_xp;
        int t = blockIdx.x * 256 + threadIdx.x;
        int lane = t & 31, kb = (t >> 5) & 63, rb = t >> 11;
        int g = lane >> 2, tq = lane & 3;
        const float* s = src + (rb * 16 + g) * KK + kb * 16 + tq * 2;
        float2 v00 = *reinterpret_cast<const float2*>(s);
        float2 v10 = *reinterpret_cast<const float2*>(s + 8 * KK);
        float2 v01 = *reinterpret_cast<const float2*>(s + 8);
        float2 v11 = *reinterpret_cast<const float2*>(s + 8 * KK + 8);
        uint4 o;
        o.x = h2u(v00.x, v00.y);
        o.y = h2u(v10.x, v10.y);
        o.z = h2u(v01.x, v01.y);
        o.w = h2u(v11.x, v11.y);
        dst[t] = o;
    } else {
        if (blockIdx.x >= 1024) return;
        const float* srcs[6] = {w0, w1, w2, w3, w4, w5};
        int widx = blockIdx.y - 2;
        const float* src = srcs[widx];
        uint2* dst = g_Wh[widx];
        int t = blockIdx.x * 256 + threadIdx.x;
        int lane = t & 31, kb = (t >> 5) & 63, nb = t >> 11;
        int g = lane >> 2, tq = lane & 3;
        const float* s = src + (nb * 8 + g) * KK + kb * 16 + tq * 2;
        float2 v0 = *reinterpret_cast<const float2*>(s);
        float2 v1 = *reinterpret_cast<const float2*>(s + 8);
        uint2 o;
        o.x = h2u(v0.x, v0.y);
        o.y = h2u(v1.x, v1.y);
        dst[t] = o;
    }
}

// ---------------------------------------------------------------------------
// Kernel 1: dual-acc z/r GEMM. Block 128x64, 8 warps (4m x 2n), warp 32x32
// dual, BK=64. A staged (2 x 16KB smem); Bz/Br direct LDG from g_Wh.
// ---------------------------------------------------------------------------
__global__ void __launch_bounds__(256, 2) gemm_zr(const float* __restrict__ h) {
    extern __shared__ uint4 sm4[];
    const int tid = threadIdx.x, wid = tid >> 5, lane = tid & 31;
    const int g = lane >> 2, tq = lane & 3;
    const int bn = blockIdx.x * 64, bm = blockIdx.y * 128;   // x = n (L2 A-reuse)
    const int rb0 = bm >> 4, nb0 = bn >> 3;

    auto stageA = [&](int t) {
        const int seg = t >> 4, kb = (t & 15) * 4;
        const uint4* Ag = seg ? g_hp : g_xp;
        uint4* dst = &sm4[(t & 1) * 1024];
        #pragma unroll
        for (int i = 0; i < 4; i++) {
            int c = tid + i * 256, rbl = c >> 7, rem = c & 127;
            cp_async16(&dst[c], &Ag[((rb0 + rbl) * 64 + kb) * 32 + rem]);
        }
        cp_commit();
    };

    float accZ[2][4][4] = {}, accR[2][4][4] = {};
    stageA(0);

    const int r0 = (wid & 3) * 2, nbl = (wid >> 2) * 4;
    for (int t = 0; t < 32; t++) {
        cp_wait_all();
        __syncthreads();
        if (t + 1 < 32) stageA(t + 1);
        const int seg = t >> 4, kb0 = (t & 15) * 4;
        const uint4* A_ = &sm4[(t & 1) * 1024];
        const uint2* BzT = reinterpret_cast<const uint2*>(g_Wh[seg ? 1 : 0]);
        const uint2* BrT = reinterpret_cast<const uint2*>(g_Wh[seg ? 3 : 2]);
        #pragma unroll
        for (int kk = 0; kk < 4; kk++) {
            uint4 a0 = A_[(r0 * 4 + kk) * 32 + lane];
            uint4 a1 = A_[((r0 + 1) * 4 + kk) * 32 + lane];
            #pragma unroll
            for (int nt = 0; nt < 4; nt++) {
                int bi = ((nb0 + nbl + nt) * 64 + kb0 + kk) * 32 + lane;
                uint2 bz = BzT[bi];
                uint2 br = BrT[bi];
                mma16(accZ[0][nt], a0, bz);
                mma16(accZ[1][nt], a1, bz);
                mma16(accR[0][nt], a0, br);
                mma16(accR[1][nt], a1, br);
            }
        }
        __syncthreads();
    }

    // epilogue: z f32; rh fp16 fragment-ordered (validated R4)
    uint32_t* rhp32 = reinterpret_cast<uint32_t*>(g_rhp);
    const int wm = (wid & 3) * 32, wn = (wid >> 2) * 32;
    #pragma unroll
    for (int mt = 0; mt < 2; mt++) {
        const int rbase = bm + wm + mt * 16;
        #pragma unroll
        for (int nt = 0; nt < 4; nt++) {
            const int colb = bn + wn + nt * 8 + tq * 2;
            const int kb = ((bn + wn) >> 4) + (nt >> 1);
            #pragma unroll
            for (int half = 0; half < 2; half++) {
                const int row = rbase + half * 8 + g;
                const int idx = row * HH + colb;
                float2 hv = *reinterpret_cast<const float2*>(&h[idx]);
                float2 zo;
                zo.x = sig_(accZ[mt][nt][half * 2]);
                zo.y = sig_(accZ[mt][nt][half * 2 + 1]);
                *reinterpret_cast<float2*>(&g_Z[idx]) = zo;
                float rh0 = sig_(accR[mt][nt][half * 2]) * hv.x;
                float rh1 = sig_(accR[mt][nt][half * 2 + 1]) * hv.y;
                const int rbm = (rbase >> 4);
                const int regidx = half + 2 * (nt & 1);
                rhp32[((rbm * 64 + kb) * 32 + lane) * 4 + regidx] = h2u(rh0, rh1);
            }
        }
    }
}

// ---------------------------------------------------------------------------
// Kernel 2: block 128x64, 8 warps (4m x 2n), warp 32x32, BK=64.
// A staged (2 x 16KB smem); B direct LDG. 3 CTAs/SM.
// ---------------------------------------------------------------------------
__global__ void __launch_bounds__(256, 3) gemm_ht(const float* __restrict__ h,
                                                  float* __restrict__ out) {
    extern __shared__ uint4 sm4[];
    const int tid = threadIdx.x, wid = tid >> 5, lane = tid & 31;
    const int g = lane >> 2, tq = lane & 3;
    const int mrow = wid & 3, ncol = wid >> 2;   // 4 x 2 warps, warp 32x32
    const int bn = blockIdx.x * 64, bm = blockIdx.y * 128;   // x = n
    const int rb0 = bm >> 4, nb0 = bn >> 3;

    auto stageA = [&](int t) {
        const int seg = t >> 4, kb0 = (t & 15) * 4;
        const uint4* Ag = seg ? g_xp : g_rhp;
        uint4* dst = &sm4[(t & 1) * 1024];
        #pragma unroll
        for (int i = 0; i < 4; i++) {
            int c = tid + i * 256, rbl = c >> 7, rem = c & 127;
            cp_async16(&dst[c], &Ag[((rb0 + rbl) * 64 + kb0) * 32 + rem]);
        }
        cp_commit();
    };

    float acc[2][4][4] = {};
    stageA(0);

    for (int t = 0; t < 32; t++) {
        cp_wait_all();
        __syncthreads();
        if (t + 1 < 32) stageA(t + 1);
        const int seg = t >> 4, kb0 = (t & 15) * 4;
        const uint4* A_ = &sm4[(t & 1) * 1024];
        const uint2* BT = reinterpret_cast<const uint2*>(g_Wh[seg ? 5 : 4]);
        #pragma unroll
        for (int kk = 0; kk < 4; kk++) {
            uint4 a0 = A_[((mrow * 2 + 0) * 4 + kk) * 32 + lane];
            uint4 a1 = A_[((mrow * 2 + 1) * 4 + kk) * 32 + lane];
            #pragma unroll
            for (int n = 0; n < 4; n++) {
                uint2 b = BT[((nb0 + ncol * 4 + n) * 64 + kb0 + kk) * 32 + lane];
                mma16(acc[0][n], a0, b);
                mma16(acc[1][n], a1, b);
            }
        }
        __syncthreads();
    }

    #pragma unroll
    for (int r = 0; r < 2; r++) {
        const int rowbase = bm + mrow * 32 + r * 16;
        #pragma unroll
        for (int n = 0; n < 4; n++) {
            const int col = bn + ncol * 32 + n * 8 + tq * 2;
            #pragma unroll
            for (int half = 0; half < 2; half++) {
                const int idx = (rowbase + half * 8 + g) * HH + col;
                float2 hv = *reinterpret_cast<const float2*>(&h[idx]);
                float2 zv = *reinterpret_cast<const float2*>(&g_Z[idx]);
                float2 ov;
                ov.x = zv.x * hv.x + (1.0f - zv.x) * ftanh_(acc[r][n][half * 2]);
                ov.y = zv.y * hv.y + (1.0f - zv.y) * ftanh_(acc[r][n][half * 2 + 1]);
                *reinterpret_cast<float2*>(&out[idx]) = ov;
            }
        }
    }
}

// ---------------------------------------------------------------------------
extern "C" void kernel_launch(void* const* d_in, const int* in_sizes, int n_in,
                              void* d_out, int out_size) {
    const float* x   = (const float*)d_in[0];
    const float* h   = (const float*)d_in[1];
    const float* Wwz = (const float*)d_in[2];
    const float* Wuz = (const float*)d_in[3];
    const float* Wwr = (const float*)d_in[4];
    const float* Wur = (const float*)d_in[5];
    const float* Wu  = (const float*)d_in[6];
    const float* Ww  = (const float*)d_in[7];
    float* out = (float*)d_out;

    const int smem = 2048 * 16;   // 32 KB (A double buffer only)
    cudaFuncSetAttribute(gemm_zr, cudaFuncAttributeMaxDynamicSharedMemorySize, smem);
    cudaFuncSetAttribute(gemm_ht, cudaFuncAttributeMaxDynamicSharedMemorySize, smem);

    perm_all<<<dim3(4096, 8), 256>>>(x, h, Wwz, Wuz, Wwr, Wur, Wu, Ww);
    gemm_zr<<<dim3(16, 64), 256, smem>>>(h);
    gemm_ht<<<dim3(16, 64), 256, smem>>>(h, out);
}

// round 11
// speedup vs baseline: 1.1935x; 1.1935x over previous
#include <cuda_runtime.h>
#include <cuda_fp16.h>
#include <cstdint>

// GRU cell B=8192, I=H=1024 fp32. mma.sync fp16 m16n8k16 (fp32 accum).
// R11: GEMMs = R9 verbatim (best). perm remapped so g = warp-id -> every
// warp's loads are contiguous 512B spans (was 8-way line-split gathers).

#define BB 8192
#define HH 1024
#define KK 1024

// Fragment layouts (validated R4):
//  A: g_ap[((rb*64+kb)*32+lane)] = uint4{a0,a1,a2,a3}, lane=g*4+tq
//  B: g_Wh[w][((nb*64+kb)*32+lane)] = uint2{b0,b1}
__device__ __align__(16) uint4 g_xp[BB * KK / 8];
__device__ __align__(16) uint4 g_hp[BB * KK / 8];
__device__ __align__(16) uint4 g_rhp[BB * KK / 8];
__device__ __align__(16) float g_Z[BB * HH];
__device__ __align__(16) uint2 g_Wh[6][HH * KK / 4];  // 0:Wwz 1:Wuz 2:Wwr 3:Wur 4:Wu 5:Ww

__device__ __forceinline__ void cp_async16(void* sdst, const void* gsrc) {
    uint32_t s = (uint32_t)__cvta_generic_to_shared(sdst);
    asm volatile("cp.async.cg.shared.global [%0], [%1], 16;\n" :: "r"(s), "l"(gsrc));
}
__device__ __forceinline__ void cp_commit() { asm volatile("cp.async.commit_group;\n"); }
__device__ __forceinline__ void cp_wait1() { asm volatile("cp.async.wait_group 1;\n"); }
__device__ __forceinline__ void cp_wait0() { asm volatile("cp.async.wait_group 0;\n"); }

__device__ __forceinline__ void mma16(float c[4], const uint4& a, const uint2& b) {
    asm volatile(
        "mma.sync.aligned.m16n8k16.row.col.f32.f16.f16.f32 "
        "{%0,%1,%2,%3},{%4,%5,%6,%7},{%8,%9},{%0,%1,%2,%3};\n"
        : "+f"(c[0]), "+f"(c[1]), "+f"(c[2]), "+f"(c[3])
        : "r"(a.x), "r"(a.y), "r"(a.z), "r"(a.w), "r"(b.x), "r"(b.y));
}
__device__ __forceinline__ float sig_(float v) { return 1.0f / (1.0f + __expf(-v)); }
__device__ __forceinline__ float ftanh_(float v) {
    return 1.0f - 2.0f / (1.0f + __expf(2.0f * v));
}
__device__ __forceinline__ uint32_t h2u(float a, float b) {
    __half2 h = __floats2half2_rn(a, b);
    return *reinterpret_cast<uint32_t*>(&h);
}

// ---------------------------------------------------------------------------
// Preprocess (R11): g = warp-id, (kb_sub, tq) = lane -> coalesced loads.
//  y in {0,1}: A tensors (x, h); grid.x = 512 rb * 8 kb-chunks = 4096
//  y in [2,8): weights;         grid.x = 128 nb * 8 kb-chunks = 1024
// Output layout identical to R4.
// ---------------------------------------------------------------------------
__global__ void __launch_bounds__(256) perm_all(
    const float* __restrict__ x, const float* __restrict__ hm,
    const float* __restrict__ w0, const float* __restrict__ w1,
    const float* __restrict__ w2, const float* __restrict__ w3,
    const float* __restrict__ w4, const float* __restrict__ w5) {
    const int t = threadIdx.x;
    const int g = t >> 5;                  // warp id = fragment row-group
    const int l = t & 31;
    const int kb_sub = l >> 2, tq = l & 3;

    if (blockIdx.y < 2) {
        const float* src = blockIdx.y ? hm : x;
        uint4* dst = blockIdx.y ? g_hp : g_xp;
        const int rb = blockIdx.x >> 3, kbc = blockIdx.x & 7;
        const int kb = kbc * 8 + kb_sub;
        const int r0 = rb * 16 + g;
        const int c0 = kb * 16 + tq * 2;
        const float* s0 = src + r0 * KK + c0;
        const float* s1 = s0 + 8 * KK;
        float2 v00 = *reinterpret_cast<const float2*>(s0);
        float2 v01 = *reinterpret_cast<const float2*>(s0 + 8);
        float2 v10 = *reinterpret_cast<const float2*>(s1);
        float2 v11 = *reinterpret_cast<const float2*>(s1 + 8);
        uint4 o;
        o.x = h2u(v00.x, v00.y);
        o.y = h2u(v10.x, v10.y);
        o.z = h2u(v01.x, v01.y);
        o.w = h2u(v11.x, v11.y);
        dst[(rb * 64 + kb) * 32 + g * 4 + tq] = o;
    } else {
        if (blockIdx.x >= 1024) return;
        const float* srcs[6] = {w0, w1, w2, w3, w4, w5};
        const int widx = blockIdx.y - 2;
        const float* src = srcs[widx];
        uint2* dst = g_Wh[widx];
        const int nb = blockIdx.x >> 3, kbc = blockIdx.x & 7;
        const int kb = kbc * 8 + kb_sub;
        const float* s = src + (nb * 8 + g) * KK + kb * 16 + tq * 2;
        float2 v0 = *reinterpret_cast<const float2*>(s);
        float2 v1 = *reinterpret_cast<const float2*>(s + 8);
        uint2 o;
        o.x = h2u(v0.x, v0.y);
        o.y = h2u(v1.x, v1.y);
        dst[(nb * 64 + kb) * 32 + g * 4 + tq] = o;
    }
}

// ---------------------------------------------------------------------------
// Kernel 1 (R9 verbatim): dual-acc z/r GEMM. Block 128x64, 8 warps (4m x 2n),
// warp 32x32 dual, BK=64, 3-stage ring. smem/stage (uint4): A 1024 | Bz 512 |
// Br 512. 3 stages = 96KB, 2 CTAs/SM.
// ---------------------------------------------------------------------------
__global__ void __launch_bounds__(256, 2) gemm_zr(const float* __restrict__ h) {
    extern __shared__ uint4 sm4[];
    const int tid = threadIdx.x, wid = tid >> 5, lane = tid & 31;
    const int g = lane >> 2, tq = lane & 3;
    const int bm = blockIdx.x * 128, bn = blockIdx.y * 64;
    const int rb0 = bm >> 4, nb0 = bn >> 3;

    auto stage = [&](int t) {
        const int seg = t >> 4, kb = (t & 15) * 4;
        const uint4* Ag = seg ? g_hp : g_xp;
        const uint4* Bz = reinterpret_cast<const uint4*>(g_Wh[seg ? 1 : 0]);
        const uint4* Br = reinterpret_cast<const uint4*>(g_Wh[seg ? 3 : 2]);
        uint4* dst = &sm4[(t % 3) * 2048];
        #pragma unroll
        for (int i = 0; i < 4; i++) {
            int c = tid + i * 256, rbl = c >> 7, rem = c & 127;
            cp_async16(&dst[c], &Ag[((rb0 + rbl) * 64 + kb) * 32 + rem]);
        }
        #pragma unroll
        for (int i = 0; i < 2; i++) {
            int c = tid + i * 256, nbl = c >> 6, rem = c & 63;
            int so = ((nb0 + nbl) * 64 + kb) * 16 + rem;
            cp_async16(&dst[1024 + c], &Bz[so]);
            cp_async16(&dst[1536 + c], &Br[so]);
        }
        cp_commit();
    };

    float accZ[2][4][4] = {}, accR[2][4][4] = {};
    stage(0);
    stage(1);

    const int r0 = (wid & 3) * 2, nbl = (wid >> 2) * 4;
    for (int t = 0; t < 32; t++) {
        if (t + 2 < 32) cp_wait1(); else cp_wait0();
        __syncthreads();
        if (t + 2 < 32) stage(t + 2);
        const uint4* A_ = &sm4[(t % 3) * 2048];
        const uint2* Bz_ = reinterpret_cast<const uint2*>(&A_[1024]);
        const uint2* Br_ = reinterpret_cast<const uint2*>(&A_[1536]);
        #pragma unroll
        for (int kk = 0; kk < 4; kk++) {
            uint4 a0 = A_[(r0 * 4 + kk) * 32 + lane];
            uint4 a1 = A_[((r0 + 1) * 4 + kk) * 32 + lane];
            #pragma unroll
            for (int nt = 0; nt < 4; nt++) {
                uint2 bz = Bz_[(nbl + nt) * 128 + kk * 32 + lane];
                uint2 br = Br_[(nbl + nt) * 128 + kk * 32 + lane];
                mma16(accZ[0][nt], a0, bz);
                mma16(accZ[1][nt], a1, bz);
                mma16(accR[0][nt], a0, br);
                mma16(accR[1][nt], a1, br);
            }
        }
    }

    // epilogue: z f32; rh fp16 fragment-ordered (validated R4)
    uint32_t* rhp32 = reinterpret_cast<uint32_t*>(g_rhp);
    const int wm = (wid & 3) * 32, wn = (wid >> 2) * 32;
    #pragma unroll
    for (int mt = 0; mt < 2; mt++) {
        const int rbase = bm + wm + mt * 16;
        #pragma unroll
        for (int nt = 0; nt < 4; nt++) {
            const int colb = bn + wn + nt * 8 + tq * 2;
            const int kb = ((bn + wn) >> 4) + (nt >> 1);
            #pragma unroll
            for (int half = 0; half < 2; half++) {
                const int row = rbase + half * 8 + g;
                const int idx = row * HH + colb;
                float2 hv = *reinterpret_cast<const float2*>(&h[idx]);
                float2 zo;
                zo.x = sig_(accZ[mt][nt][half * 2]);
                zo.y = sig_(accZ[mt][nt][half * 2 + 1]);
                *reinterpret_cast<float2*>(&g_Z[idx]) = zo;
                float rh0 = sig_(accR[mt][nt][half * 2]) * hv.x;
                float rh1 = sig_(accR[mt][nt][half * 2 + 1]) * hv.y;
                const int rbm = (rbase >> 4);
                const int regidx = half + 2 * (nt & 1);
                rhp32[((rbm * 64 + kb) * 32 + lane) * 4 + regidx] = h2u(rh0, rh1);
            }
        }
    }
}

// ---------------------------------------------------------------------------
// Kernel 2 (R9 verbatim): block 128x64, 8 warps (4m x 2n), warp 32x32, BK=64,
// 3-stage ring. smem/stage (uint4): A 1024 | B 512. 72KB, 3 CTAs/SM.
// ---------------------------------------------------------------------------
__global__ void __launch_bounds__(256, 3) gemm_ht(const float* __restrict__ h,
                                                  float* __restrict__ out) {
    extern __shared__ uint4 sm4[];
    const int tid = threadIdx.x, wid = tid >> 5, lane = tid & 31;
    const int g = lane >> 2, tq = lane & 3;
    const int mrow = wid & 3, ncol = wid >> 2;   // 4 x 2 warps, warp 32x32
    const int bm = blockIdx.x * 128, bn = blockIdx.y * 64;
    const int rb0 = bm >> 4, nb0 = bn >> 3;

    auto stage = [&](int t) {
        const int seg = t >> 4, kb0 = (t & 15) * 4;
        const uint4* Ag = seg ? g_xp : g_rhp;
        const uint4* Bg = reinterpret_cast<const uint4*>(g_Wh[seg ? 5 : 4]);
        uint4* dst = &sm4[(t % 3) * 1536];
        #pragma unroll
        for (int i = 0; i < 4; i++) {
            int c = tid + i * 256, rbl = c >> 7, rem = c & 127;
            cp_async16(&dst[c], &Ag[((rb0 + rbl) * 64 + kb0) * 32 + rem]);
        }
        #pragma unroll
        for (int i = 0; i < 2; i++) {
            int c = tid + i * 256, nbl = c >> 6, rem = c & 63;
            cp_async16(&dst[1024 + c], &Bg[((nb0 + nbl) * 64 + kb0) * 16 + rem]);
        }
        cp_commit();
    };

    float acc[2][4][4] = {};
    stage(0);
    stage(1);

    for (int t = 0; t < 32; t++) {
        if (t + 2 < 32) cp_wait1(); else cp_wait0();
        __syncthreads();
        if (t + 2 < 32) stage(t + 2);
        const uint4* A_ = &sm4[(t % 3) * 1536];
        const uint2* B_ = reinterpret_cast<const uint2*>(&A_[1024]);
        #pragma unroll
        for (int kk = 0; kk < 4; kk++) {
            uint4 a0 = A_[((mrow * 2 + 0) * 4 + kk) * 32 + lane];
            uint4 a1 = A_[((mrow * 2 + 1) * 4 + kk) * 32 + lane];
            #pragma unroll
            for (int n = 0; n < 4; n++) {
                uint2 b = B_[((ncol * 4 + n) * 4 + kk) * 32 + lane];
                mma16(acc[0][n], a0, b);
                mma16(acc[1][n], a1, b);
            }
        }
    }

    #pragma unroll
    for (int r = 0; r < 2; r++) {
        const int rowbase = bm + mrow * 32 + r * 16;
        #pragma unroll
        for (int n = 0; n < 4; n++) {
            const int col = bn + ncol * 32 + n * 8 + tq * 2;
            #pragma unroll
            for (int half = 0; half < 2; half++) {
                const int idx = (rowbase + half * 8 + g) * HH + col;
                float2 hv = *reinterpret_cast<const float2*>(&h[idx]);
                float2 zv = *reinterpret_cast<const float2*>(&g_Z[idx]);
                float2 ov;
                ov.x = zv.x * hv.x + (1.0f - zv.x) * ftanh_(acc[r][n][half * 2]);
                ov.y = zv.y * hv.y + (1.0f - zv.y) * ftanh_(acc[r][n][half * 2 + 1]);
                *reinterpret_cast<float2*>(&out[idx]) = ov;
            }
        }
    }
}

// ---------------------------------------------------------------------------
extern "C" void kernel_launch(void* const* d_in, const int* in_sizes, int n_in,
                              void* d_out, int out_size) {
    const float* x   = (const float*)d_in[0];
    const float* h   = (const float*)d_in[1];
    const float* Wwz = (const float*)d_in[2];
    const float* Wuz = (const float*)d_in[3];
    const float* Wwr = (const float*)d_in[4];
    const float* Wur = (const float*)d_in[5];
    const float* Wu  = (const float*)d_in[6];
    const float* Ww  = (const float*)d_in[7];
    float* out = (float*)d_out;

    const int s1 = 6144 * 16;   // 96 KB
    const int s2 = 4608 * 16;   // 72 KB
    cudaFuncSetAttribute(gemm_zr, cudaFuncAttributeMaxDynamicSharedMemorySize, s1);
    cudaFuncSetAttribute(gemm_ht, cudaFuncAttributeMaxDynamicSharedMemorySize, s2);

    perm_all<<<dim3(4096, 8), 256>>>(x, h, Wwz, Wuz, Wwr, Wur, Wu, Ww);
    gemm_zr<<<dim3(64, 16), 256, s1>>>(h);
    gemm_ht<<<dim3(64, 16), 256, s2>>>(h, out);
}